// round 8
// baseline (speedup 1.0000x reference)
#include <cuda_runtime.h>
#include <cstdint>
#include <cstddef>

// ---------------- problem constants ----------------
#define N_NODES 50000
#define E_EDGES 800000
#define E2      (E_EDGES + N_NODES)   // 850000 (self-loops appended)
#define E_DIM   101
#define E_PAD   104                   // padded so each row is 16B-aligned
#define HC      128
#define NHEAD   4
#define NEG     0.2f

// ---------------- scratch (static device globals; no allocation) ----------------
__device__ float g_xl  [(size_t)N_NODES * HC];
__device__ float g_xr  [(size_t)N_NODES * HC];
__device__ float g_h   [(size_t)N_NODES * HC];
__device__ float g_out [(size_t)N_NODES * HC];
__device__ float g_mlp [(size_t)N_NODES * HC];
__device__ float g_loop[(size_t)N_NODES * E_PAD];
__device__ float g_cnt [N_NODES];
__device__ float g_logit[(size_t)E2 * NHEAD];
__device__ float g_amax[(size_t)N_NODES * NHEAD];
__device__ float g_den [(size_t)N_NODES * NHEAD];
__device__ int   g_src [E_EDGES];
__device__ int   g_dst [E_EDGES];
__device__ int   g_idx64;

// ---------------- helpers ----------------
__device__ __forceinline__ void red_add_v4(float* addr, float4 v) {
    asm volatile("red.global.add.v4.f32 [%0], {%1, %2, %3, %4};"
                 :: "l"(addr), "f"(v.x), "f"(v.y), "f"(v.z), "f"(v.w)
                 : "memory");
}

__device__ __forceinline__ void atomicMaxFloat(float* addr, float value) {
    if (value >= 0.0f) {
        atomicMax((int*)addr, __float_as_int(value));
    } else {
        atomicMin((unsigned int*)addr, __float_as_uint(value));
    }
}

__device__ __forceinline__ float leaky(float x) {
    return x > 0.0f ? x : NEG * x;
}

// ---------------- edge-index dtype detection + canonicalization ----------------
// If edge_index is int64 (values < 2^31), every odd int32 word (hi half) is 0.
// If it is int32, those positions hold random node ids -> some nonzero.
__global__ void k_detect(const int* __restrict__ ei32) {
    __shared__ int found;
    if (threadIdx.x == 0) found = 0;
    __syncthreads();
    for (int i = threadIdx.x; i < 4096; i += blockDim.x) {
        if (ei32[2 * i + 1] != 0) found = 1;
    }
    __syncthreads();
    if (threadIdx.x == 0) g_idx64 = (found == 0) ? 1 : 0;
}

__global__ void k_convert(const void* __restrict__ ei) {
    int i = blockIdx.x * blockDim.x + threadIdx.x;
    if (i >= E_EDGES) return;
    if (g_idx64) {
        const long long* p = (const long long*)ei;
        g_src[i] = (int)p[i];
        g_dst[i] = (int)p[(size_t)E_EDGES + i];
    } else {
        const int* p = (const int*)ei;
        g_src[i] = p[i];
        g_dst[i] = p[E_EDGES + i];
    }
}

// ---------------- generic fill ----------------
__global__ void k_fill(float* __restrict__ p, float v, int n) {
    int i = blockIdx.x * blockDim.x + threadIdx.x;
    if (i < n) p[i] = v;
}

// ---------------- degree + loop_attr sum (warp per edge) ----------------
__global__ void k_degree(const float* __restrict__ ea) {
    int lane = threadIdx.x & 31;
    int w    = (blockIdx.x * blockDim.x + threadIdx.x) >> 5;
    int nw   = (gridDim.x * blockDim.x) >> 5;
    for (int e = w; e < E_EDGES; e += nw) {
        int d = g_dst[e];
        const float* row = ea + (size_t)e * E_DIM;
        float* outp = g_loop + (size_t)d * E_PAD;
        if (lane < 25) {
            int j = lane * 4;
            float4 v;
            v.x = row[j]; v.y = row[j + 1]; v.z = row[j + 2]; v.w = row[j + 3];
            red_add_v4(outp + j, v);
        } else if (lane == 25) {
            atomicAdd(outp + 100, row[100]);
        } else if (lane == 26) {
            atomicAdd(&g_cnt[d], 1.0f);
        }
    }
}

__global__ void k_loopdiv() {
    int i = blockIdx.x * blockDim.x + threadIdx.x;
    if (i >= N_NODES * E_PAD) return;
    int n = i / E_PAD;
    float c = fmaxf(g_cnt[n], 1.0f);
    g_loop[i] = g_loop[i] / c;
}

// ---------------- node GEMM: out[r,:] = in[r,:] @ W(128x128) + b ----------------
__global__ void k_gemm128(const float* __restrict__ in, const float* __restrict__ W,
                          const float* __restrict__ bias, float* __restrict__ out,
                          int nrows, int doRelu) {
    extern __shared__ float sW[];   // 128*128 floats = 64KB
    for (int i = threadIdx.x; i < 128 * 128; i += blockDim.x) sW[i] = W[i];
    __syncthreads();
    const float4* sW4 = (const float4*)sW;
    int lane = threadIdx.x & 31;
    int w    = (blockIdx.x * blockDim.x + threadIdx.x) >> 5;
    int nw   = (gridDim.x * blockDim.x) >> 5;
    float4 bq = ((const float4*)bias)[lane];

    for (int r = w; r < nrows; r += nw) {
        const float* row = in + (size_t)r * 128;
        float a[4];
        a[0] = row[lane]; a[1] = row[lane + 32]; a[2] = row[lane + 64]; a[3] = row[lane + 96];
        float4 acc = bq;
#pragma unroll
        for (int j = 0; j < 4; ++j) {
#pragma unroll
            for (int kk = 0; kk < 32; ++kk) {
                float ak = __shfl_sync(0xffffffffu, a[j], kk);
                float4 wv = sW4[(j * 32 + kk) * 32 + lane];
                acc.x += ak * wv.x; acc.y += ak * wv.y;
                acc.z += ak * wv.z; acc.w += ak * wv.w;
            }
        }
        if (doRelu) {
            acc.x = fmaxf(acc.x, 0.f); acc.y = fmaxf(acc.y, 0.f);
            acc.z = fmaxf(acc.z, 0.f); acc.w = fmaxf(acc.w, 0.f);
        }
        ((float4*)(out + (size_t)r * 128))[lane] = acc;
    }
}

// ---------------- edge logit: fused ea@We + leaky + att dot + atomic max ----------------
// warp processes 4 edges; We in dynamic smem (101*128 f32 = 51712B)
__global__ void k_edge_logit(const float* __restrict__ ea,
                             const float* __restrict__ We,
                             const float* __restrict__ att) {
    extern __shared__ float sWe[];
    for (int i = threadIdx.x; i < E_DIM * HC; i += blockDim.x) sWe[i] = We[i];
    __syncthreads();
    const float4* sWe4 = (const float4*)sWe;

    int lane = threadIdx.x & 31;
    int w    = (blockIdx.x * blockDim.x + threadIdx.x) >> 5;
    int nw   = (gridDim.x * blockDim.x) >> 5;
    float4 attq = ((const float4*)att)[lane];   // channel c = lane*4+q, head = lane>>3

    for (int base = w * 4; base < E2; base += nw * 4) {
        float  av[4][4];
        float4 acc[4];
        int    dd[4];
        bool   val[4];
#pragma unroll
        for (int i = 0; i < 4; ++i) {
            int e = base + i;
            val[i] = (e < E2);
            if (!val[i]) e = 0;
            int s, d; const float* row;
            if (e < E_EDGES) {
                s = g_src[e]; d = g_dst[e];
                row = ea + (size_t)e * E_DIM;
            } else {
                s = e - E_EDGES; d = s;
                row = g_loop + (size_t)s * E_PAD;
            }
            dd[i] = d;
            av[i][0] = row[lane];
            av[i][1] = row[lane + 32];
            av[i][2] = row[lane + 64];
            av[i][3] = (lane + 96 < E_DIM) ? row[lane + 96] : 0.0f;
            float4 xlv = ((const float4*)(g_xl + (size_t)s * 128))[lane];
            float4 xrv = ((const float4*)(g_xr + (size_t)d * 128))[lane];
            acc[i] = make_float4(xlv.x + xrv.x, xlv.y + xrv.y, xlv.z + xrv.z, xlv.w + xrv.w);
        }
        // full 32-wide K segments
#pragma unroll
        for (int j = 0; j < 3; ++j) {
#pragma unroll
            for (int kk = 0; kk < 32; ++kk) {
                float4 wv = sWe4[(j * 32 + kk) * 32 + lane];
#pragma unroll
                for (int i = 0; i < 4; ++i) {
                    float ak = __shfl_sync(0xffffffffu, av[i][j], kk);
                    acc[i].x += ak * wv.x; acc[i].y += ak * wv.y;
                    acc[i].z += ak * wv.z; acc[i].w += ak * wv.w;
                }
            }
        }
        // tail: k = 96..100
#pragma unroll
        for (int kk = 0; kk < 5; ++kk) {
            float4 wv = sWe4[(96 + kk) * 32 + lane];
#pragma unroll
            for (int i = 0; i < 4; ++i) {
                float ak = __shfl_sync(0xffffffffu, av[i][3], kk);
                acc[i].x += ak * wv.x; acc[i].y += ak * wv.y;
                acc[i].z += ak * wv.z; acc[i].w += ak * wv.w;
            }
        }
        // epilogue: leaky-relu, dot with att, 8-lane head reduce
#pragma unroll
        for (int i = 0; i < 4; ++i) {
            float p = leaky(acc[i].x) * attq.x + leaky(acc[i].y) * attq.y
                    + leaky(acc[i].z) * attq.z + leaky(acc[i].w) * attq.w;
            p += __shfl_down_sync(0xffffffffu, p, 4);
            p += __shfl_down_sync(0xffffffffu, p, 2);
            p += __shfl_down_sync(0xffffffffu, p, 1);
            if (val[i] && (lane & 7) == 0) {
                int h = lane >> 3;
                int e = base + i;
                g_logit[(size_t)e * NHEAD + h] = p;
                atomicMaxFloat(&g_amax[(size_t)dd[i] * NHEAD + h], p);
            }
        }
    }
}

// ---------------- exp + denominator accumulation (thread per edge) ----------------
__global__ void k_edge_den() {
    int e = blockIdx.x * blockDim.x + threadIdx.x;
    if (e >= E2) return;
    int d = (e < E_EDGES) ? g_dst[e] : (e - E_EDGES);
    float4 lg = ((const float4*)g_logit)[e];
    float4 mx = ((const float4*)g_amax)[d];
    float4 ex;
    ex.x = __expf(lg.x - mx.x);
    ex.y = __expf(lg.y - mx.y);
    ex.z = __expf(lg.z - mx.z);
    ex.w = __expf(lg.w - mx.w);
    ((float4*)g_logit)[e] = ex;          // overwrite logits with exp values
    red_add_v4(&g_den[(size_t)d * NHEAD], ex);
}

// ---------------- weighted aggregation (warp per edge) ----------------
__global__ void k_edge_agg() {
    int lane = threadIdx.x & 31;
    int w    = (blockIdx.x * blockDim.x + threadIdx.x) >> 5;
    int nw   = (gridDim.x * blockDim.x) >> 5;
    for (int e = w; e < E2; e += nw) {
        int s, d;
        if (e < E_EDGES) { s = g_src[e]; d = g_dst[e]; }
        else             { s = e - E_EDGES; d = s; }
        int h = lane >> 3;
        float exv  = g_logit[(size_t)e * NHEAD + h];
        float denv = g_den[(size_t)d * NHEAD + h];
        float alpha = exv / (denv + 1e-16f);
        float4 v = ((const float4*)(g_xl + (size_t)s * 128))[lane];
        v.x *= alpha; v.y *= alpha; v.z *= alpha; v.w *= alpha;
        red_add_v4(&g_out[(size_t)d * 128 + lane * 4], v);
    }
}

// ---------------- bias + relu into next-layer input ----------------
__global__ void k_bias_relu(const float* __restrict__ bias, float* __restrict__ dst, int n) {
    int i = blockIdx.x * blockDim.x + threadIdx.x;
    if (i < n) {
        float v = g_out[i] + bias[i & 127];
        dst[i] = fmaxf(v, 0.0f);
    }
}

// ---------------- MLP tail: relu(in@W2+b2) @ W3 + b3 (warp per row) ----------------
__global__ void k_mlp_tail(const float* __restrict__ in, const float* __restrict__ W2,
                           const float* __restrict__ b2, const float* __restrict__ W3,
                           const float* __restrict__ b3, float* __restrict__ out) {
    __shared__ float sW2[128 * 64];
    __shared__ float sW3[64];
    __shared__ float sb2[64];
    for (int i = threadIdx.x; i < 128 * 64; i += blockDim.x) sW2[i] = W2[i];
    if (threadIdx.x < 64) { sW3[threadIdx.x] = W3[threadIdx.x]; sb2[threadIdx.x] = b2[threadIdx.x]; }
    __syncthreads();
    int lane = threadIdx.x & 31;
    int w    = (blockIdx.x * blockDim.x + threadIdx.x) >> 5;
    int nw   = (gridDim.x * blockDim.x) >> 5;
    float bb3 = b3[0];
    for (int r = w; r < N_NODES; r += nw) {
        const float* row = in + (size_t)r * 128;
        float a[4];
        a[0] = row[lane]; a[1] = row[lane + 32]; a[2] = row[lane + 64]; a[3] = row[lane + 96];
        float acc0 = sb2[lane * 2], acc1 = sb2[lane * 2 + 1];
#pragma unroll
        for (int j = 0; j < 4; ++j) {
#pragma unroll
            for (int kk = 0; kk < 32; ++kk) {
                float ak = __shfl_sync(0xffffffffu, a[j], kk);
                int k = j * 32 + kk;
                acc0 += ak * sW2[k * 64 + lane * 2];
                acc1 += ak * sW2[k * 64 + lane * 2 + 1];
            }
        }
        acc0 = fmaxf(acc0, 0.f); acc1 = fmaxf(acc1, 0.f);
        float p = acc0 * sW3[lane * 2] + acc1 * sW3[lane * 2 + 1];
#pragma unroll
        for (int off = 16; off; off >>= 1) p += __shfl_down_sync(0xffffffffu, p, off);
        if (lane == 0) out[r] = p + bb3;
    }
}

// ---------------- host launch ----------------
extern "C" void kernel_launch(void* const* d_in, const int* in_sizes, int n_in,
                              void* d_out, int out_size) {
    const float* x  = (const float*)d_in[0];
    const void*  ei = d_in[1];               // int32 or int64 — detected on device
    const float* ea = (const float*)d_in[2];
    const float* c1_Wl  = (const float*)d_in[3];
    const float* c1_bl  = (const float*)d_in[4];
    const float* c1_Wr  = (const float*)d_in[5];
    const float* c1_br  = (const float*)d_in[6];
    const float* c1_We  = (const float*)d_in[7];
    const float* c1_att = (const float*)d_in[8];
    const float* c1_bias= (const float*)d_in[9];
    const float* c2_Wl  = (const float*)d_in[10];
    const float* c2_bl  = (const float*)d_in[11];
    const float* c2_Wr  = (const float*)d_in[12];
    const float* c2_br  = (const float*)d_in[13];
    const float* c2_We  = (const float*)d_in[14];
    const float* c2_att = (const float*)d_in[15];
    const float* c2_bias= (const float*)d_in[16];
    const float* W1 = (const float*)d_in[17];
    const float* b1 = (const float*)d_in[18];
    const float* W2 = (const float*)d_in[19];
    const float* b2 = (const float*)d_in[20];
    const float* W3 = (const float*)d_in[21];
    const float* b3 = (const float*)d_in[22];
    float* outp = (float*)d_out;

    float *p_xl, *p_xr, *p_h, *p_out, *p_mlp, *p_loop, *p_cnt, *p_amax, *p_den;
    cudaGetSymbolAddress((void**)&p_xl,   g_xl);
    cudaGetSymbolAddress((void**)&p_xr,   g_xr);
    cudaGetSymbolAddress((void**)&p_h,    g_h);
    cudaGetSymbolAddress((void**)&p_out,  g_out);
    cudaGetSymbolAddress((void**)&p_mlp,  g_mlp);
    cudaGetSymbolAddress((void**)&p_loop, g_loop);
    cudaGetSymbolAddress((void**)&p_cnt,  g_cnt);
    cudaGetSymbolAddress((void**)&p_amax, g_amax);
    cudaGetSymbolAddress((void**)&p_den,  g_den);

    cudaFuncSetAttribute(k_gemm128,    cudaFuncAttributeMaxDynamicSharedMemorySize, 128 * 128 * 4);
    cudaFuncSetAttribute(k_edge_logit, cudaFuncAttributeMaxDynamicSharedMemorySize, E_DIM * HC * 4);

    const int T = 256;
    const int gemmBlocks = 444;   // 148 SMs * 3
    const int edgeBlocks = 444;
    const int aggBlocks  = 1024;

    // ---- canonicalize edge index (dtype-robust) ----
    k_detect<<<1, 256>>>((const int*)ei);
    k_convert<<<(E_EDGES + T - 1) / T, T>>>(ei);

    // ---- pre-pass: in-degree + mean incoming edge_attr (loop_attr) ----
    k_fill<<<(N_NODES + T - 1) / T, T>>>(p_cnt, 0.0f, N_NODES);
    k_fill<<<(N_NODES * E_PAD + T - 1) / T, T>>>(p_loop, 0.0f, N_NODES * E_PAD);
    k_degree<<<1024, T>>>(ea);
    k_loopdiv<<<(N_NODES * E_PAD + T - 1) / T, T>>>();

    for (int layer = 0; layer < 2; ++layer) {
        const float* inFeat = (layer == 0) ? x : p_h;
        const float* Wl   = (layer == 0) ? c1_Wl   : c2_Wl;
        const float* bl   = (layer == 0) ? c1_bl   : c2_bl;
        const float* Wr   = (layer == 0) ? c1_Wr   : c2_Wr;
        const float* br   = (layer == 0) ? c1_br   : c2_br;
        const float* Wep  = (layer == 0) ? c1_We   : c2_We;
        const float* attp = (layer == 0) ? c1_att  : c2_att;
        const float* bp   = (layer == 0) ? c1_bias : c2_bias;

        k_gemm128<<<gemmBlocks, T, 128 * 128 * 4>>>(inFeat, Wl, bl, p_xl, N_NODES, 0);
        k_gemm128<<<gemmBlocks, T, 128 * 128 * 4>>>(inFeat, Wr, br, p_xr, N_NODES, 0);

        k_fill<<<(N_NODES * NHEAD + T - 1) / T, T>>>(p_amax, -3.0e38f, N_NODES * NHEAD);
        k_fill<<<(N_NODES * NHEAD + T - 1) / T, T>>>(p_den, 0.0f, N_NODES * NHEAD);
        k_fill<<<(N_NODES * HC + T - 1) / T, T>>>(p_out, 0.0f, N_NODES * HC);

        k_edge_logit<<<edgeBlocks, T, E_DIM * HC * 4>>>(ea, Wep, attp);
        k_edge_den<<<(E2 + T - 1) / T, T>>>();
        k_edge_agg<<<aggBlocks, T>>>();

        k_bias_relu<<<(N_NODES * HC + T - 1) / T, T>>>(bp, p_h, N_NODES * HC);
    }

    // ---- MLP head ----
    k_gemm128<<<gemmBlocks, T, 128 * 128 * 4>>>(p_h, W1, b1, p_mlp, N_NODES, 1);
    k_mlp_tail<<<gemmBlocks, T>>>(p_mlp, W2, b2, W3, b3, outp);
}

// round 9
// speedup vs baseline: 1.0015x; 1.0015x over previous
#include <cuda_runtime.h>
#include <cstdint>
#include <cstddef>

// ---------------- problem constants ----------------
#define N_NODES 50000
#define E_EDGES 800000
#define E2      (E_EDGES + N_NODES)   // 850000 (self-loops appended)
#define E_DIM   101
#define E_PAD   104                   // padded so each row is 16B-aligned
#define HC      128
#define NHEAD   4
#define NEG     0.2f

// ---------------- scratch (static device globals; no allocation) ----------------
__device__ float g_xl  [(size_t)N_NODES * HC];
__device__ float g_xr  [(size_t)N_NODES * HC];
__device__ float g_h   [(size_t)N_NODES * HC];
__device__ float g_out [(size_t)N_NODES * HC];
__device__ float g_mlp [(size_t)N_NODES * HC];
__device__ float g_loop[(size_t)N_NODES * E_PAD];
__device__ float g_cnt [N_NODES];
__device__ float g_logit[(size_t)E2 * NHEAD];
__device__ float g_amax[(size_t)N_NODES * NHEAD];
__device__ float g_den [(size_t)N_NODES * NHEAD];
__device__ int   g_src [E_EDGES];
__device__ int   g_dst [E_EDGES];
__device__ int   g_idx64;

// ---------------- helpers ----------------
__device__ __forceinline__ void red_add_v4(float* addr, float4 v) {
    asm volatile("red.global.add.v4.f32 [%0], {%1, %2, %3, %4};"
                 :: "l"(addr), "f"(v.x), "f"(v.y), "f"(v.z), "f"(v.w)
                 : "memory");
}

__device__ __forceinline__ void atomicMaxFloat(float* addr, float value) {
    if (value >= 0.0f) {
        atomicMax((int*)addr, __float_as_int(value));
    } else {
        atomicMin((unsigned int*)addr, __float_as_uint(value));
    }
}

__device__ __forceinline__ float leaky(float x) {
    return x > 0.0f ? x : NEG * x;
}

// ---------------- edge-index dtype detection + canonicalization ----------------
// If edge_index is int64 (values < 2^31), every odd int32 word (hi half) is 0.
// If it is int32, those positions hold random node ids -> some nonzero.
__global__ void k_detect(const int* __restrict__ ei32) {
    __shared__ int found;
    if (threadIdx.x == 0) found = 0;
    __syncthreads();
    for (int i = threadIdx.x; i < 4096; i += blockDim.x) {
        if (ei32[2 * i + 1] != 0) found = 1;
    }
    __syncthreads();
    if (threadIdx.x == 0) g_idx64 = (found == 0) ? 1 : 0;
}

__global__ void k_convert(const void* __restrict__ ei) {
    int i = blockIdx.x * blockDim.x + threadIdx.x;
    if (i >= E_EDGES) return;
    if (g_idx64) {
        const long long* p = (const long long*)ei;
        g_src[i] = (int)p[i];
        g_dst[i] = (int)p[(size_t)E_EDGES + i];
    } else {
        const int* p = (const int*)ei;
        g_src[i] = p[i];
        g_dst[i] = p[E_EDGES + i];
    }
}

// ---------------- generic fill ----------------
__global__ void k_fill(float* __restrict__ p, float v, int n) {
    int i = blockIdx.x * blockDim.x + threadIdx.x;
    if (i < n) p[i] = v;
}

// ---------------- degree + loop_attr sum (warp per edge) ----------------
__global__ void k_degree(const float* __restrict__ ea) {
    int lane = threadIdx.x & 31;
    int w    = (blockIdx.x * blockDim.x + threadIdx.x) >> 5;
    int nw   = (gridDim.x * blockDim.x) >> 5;
    for (int e = w; e < E_EDGES; e += nw) {
        int d = g_dst[e];
        const float* row = ea + (size_t)e * E_DIM;
        float* outp = g_loop + (size_t)d * E_PAD;
        if (lane < 25) {
            int j = lane * 4;
            float4 v;
            v.x = row[j]; v.y = row[j + 1]; v.z = row[j + 2]; v.w = row[j + 3];
            red_add_v4(outp + j, v);
        } else if (lane == 25) {
            atomicAdd(outp + 100, row[100]);
        } else if (lane == 26) {
            atomicAdd(&g_cnt[d], 1.0f);
        }
    }
}

__global__ void k_loopdiv() {
    int i = blockIdx.x * blockDim.x + threadIdx.x;
    if (i >= N_NODES * E_PAD) return;
    int n = i / E_PAD;
    float c = fmaxf(g_cnt[n], 1.0f);
    g_loop[i] = g_loop[i] / c;
}

// ---------------- node GEMM: out[r,:] = in[r,:] @ W(128x128) + b ----------------
__global__ void k_gemm128(const float* __restrict__ in, const float* __restrict__ W,
                          const float* __restrict__ bias, float* __restrict__ out,
                          int nrows, int doRelu) {
    extern __shared__ float sW[];   // 128*128 floats = 64KB
    for (int i = threadIdx.x; i < 128 * 128; i += blockDim.x) sW[i] = W[i];
    __syncthreads();
    const float4* sW4 = (const float4*)sW;
    int lane = threadIdx.x & 31;
    int w    = (blockIdx.x * blockDim.x + threadIdx.x) >> 5;
    int nw   = (gridDim.x * blockDim.x) >> 5;
    float4 bq = ((const float4*)bias)[lane];

    for (int r = w; r < nrows; r += nw) {
        const float* row = in + (size_t)r * 128;
        float a[4];
        a[0] = row[lane]; a[1] = row[lane + 32]; a[2] = row[lane + 64]; a[3] = row[lane + 96];
        float4 acc = bq;
#pragma unroll
        for (int j = 0; j < 4; ++j) {
#pragma unroll
            for (int kk = 0; kk < 32; ++kk) {
                float ak = __shfl_sync(0xffffffffu, a[j], kk);
                float4 wv = sW4[(j * 32 + kk) * 32 + lane];
                acc.x += ak * wv.x; acc.y += ak * wv.y;
                acc.z += ak * wv.z; acc.w += ak * wv.w;
            }
        }
        if (doRelu) {
            acc.x = fmaxf(acc.x, 0.f); acc.y = fmaxf(acc.y, 0.f);
            acc.z = fmaxf(acc.z, 0.f); acc.w = fmaxf(acc.w, 0.f);
        }
        ((float4*)(out + (size_t)r * 128))[lane] = acc;
    }
}

// ---------------- edge logit: fused ea@We + leaky + att dot + atomic max ----------------
// warp processes 4 edges; We in dynamic smem (101*128 f32 = 51712B)
__global__ void k_edge_logit(const float* __restrict__ ea,
                             const float* __restrict__ We,
                             const float* __restrict__ att) {
    extern __shared__ float sWe[];
    for (int i = threadIdx.x; i < E_DIM * HC; i += blockDim.x) sWe[i] = We[i];
    __syncthreads();
    const float4* sWe4 = (const float4*)sWe;

    int lane = threadIdx.x & 31;
    int w    = (blockIdx.x * blockDim.x + threadIdx.x) >> 5;
    int nw   = (gridDim.x * blockDim.x) >> 5;
    float4 attq = ((const float4*)att)[lane];   // channel c = lane*4+q, head = lane>>3

    for (int base = w * 4; base < E2; base += nw * 4) {
        float  av[4][4];
        float4 acc[4];
        int    dd[4];
        bool   val[4];
#pragma unroll
        for (int i = 0; i < 4; ++i) {
            int e = base + i;
            val[i] = (e < E2);
            if (!val[i]) e = 0;
            int s, d; const float* row;
            if (e < E_EDGES) {
                s = g_src[e]; d = g_dst[e];
                row = ea + (size_t)e * E_DIM;
            } else {
                s = e - E_EDGES; d = s;
                row = g_loop + (size_t)s * E_PAD;
            }
            dd[i] = d;
            av[i][0] = row[lane];
            av[i][1] = row[lane + 32];
            av[i][2] = row[lane + 64];
            av[i][3] = (lane + 96 < E_DIM) ? row[lane + 96] : 0.0f;
            float4 xlv = ((const float4*)(g_xl + (size_t)s * 128))[lane];
            float4 xrv = ((const float4*)(g_xr + (size_t)d * 128))[lane];
            acc[i] = make_float4(xlv.x + xrv.x, xlv.y + xrv.y, xlv.z + xrv.z, xlv.w + xrv.w);
        }
        // full 32-wide K segments
#pragma unroll
        for (int j = 0; j < 3; ++j) {
#pragma unroll
            for (int kk = 0; kk < 32; ++kk) {
                float4 wv = sWe4[(j * 32 + kk) * 32 + lane];
#pragma unroll
                for (int i = 0; i < 4; ++i) {
                    float ak = __shfl_sync(0xffffffffu, av[i][j], kk);
                    acc[i].x += ak * wv.x; acc[i].y += ak * wv.y;
                    acc[i].z += ak * wv.z; acc[i].w += ak * wv.w;
                }
            }
        }
        // tail: k = 96..100
#pragma unroll
        for (int kk = 0; kk < 5; ++kk) {
            float4 wv = sWe4[(96 + kk) * 32 + lane];
#pragma unroll
            for (int i = 0; i < 4; ++i) {
                float ak = __shfl_sync(0xffffffffu, av[i][3], kk);
                acc[i].x += ak * wv.x; acc[i].y += ak * wv.y;
                acc[i].z += ak * wv.z; acc[i].w += ak * wv.w;
            }
        }
        // epilogue: leaky-relu, dot with att, 8-lane head reduce
#pragma unroll
        for (int i = 0; i < 4; ++i) {
            float p = leaky(acc[i].x) * attq.x + leaky(acc[i].y) * attq.y
                    + leaky(acc[i].z) * attq.z + leaky(acc[i].w) * attq.w;
            p += __shfl_down_sync(0xffffffffu, p, 4);
            p += __shfl_down_sync(0xffffffffu, p, 2);
            p += __shfl_down_sync(0xffffffffu, p, 1);
            if (val[i] && (lane & 7) == 0) {
                int h = lane >> 3;
                int e = base + i;
                g_logit[(size_t)e * NHEAD + h] = p;
                atomicMaxFloat(&g_amax[(size_t)dd[i] * NHEAD + h], p);
            }
        }
    }
}

// ---------------- exp + denominator accumulation (thread per edge) ----------------
__global__ void k_edge_den() {
    int e = blockIdx.x * blockDim.x + threadIdx.x;
    if (e >= E2) return;
    int d = (e < E_EDGES) ? g_dst[e] : (e - E_EDGES);
    float4 lg = ((const float4*)g_logit)[e];
    float4 mx = ((const float4*)g_amax)[d];
    float4 ex;
    ex.x = __expf(lg.x - mx.x);
    ex.y = __expf(lg.y - mx.y);
    ex.z = __expf(lg.z - mx.z);
    ex.w = __expf(lg.w - mx.w);
    ((float4*)g_logit)[e] = ex;          // overwrite logits with exp values
    red_add_v4(&g_den[(size_t)d * NHEAD], ex);
}

// ---------------- weighted aggregation (warp per edge) ----------------
__global__ void k_edge_agg() {
    int lane = threadIdx.x & 31;
    int w    = (blockIdx.x * blockDim.x + threadIdx.x) >> 5;
    int nw   = (gridDim.x * blockDim.x) >> 5;
    for (int e = w; e < E2; e += nw) {
        int s, d;
        if (e < E_EDGES) { s = g_src[e]; d = g_dst[e]; }
        else             { s = e - E_EDGES; d = s; }
        int h = lane >> 3;
        float exv  = g_logit[(size_t)e * NHEAD + h];
        float denv = g_den[(size_t)d * NHEAD + h];
        float alpha = exv / (denv + 1e-16f);
        float4 v = ((const float4*)(g_xl + (size_t)s * 128))[lane];
        v.x *= alpha; v.y *= alpha; v.z *= alpha; v.w *= alpha;
        red_add_v4(&g_out[(size_t)d * 128 + lane * 4], v);
    }
}

// ---------------- bias + relu into next-layer input ----------------
__global__ void k_bias_relu(const float* __restrict__ bias, float* __restrict__ dst, int n) {
    int i = blockIdx.x * blockDim.x + threadIdx.x;
    if (i < n) {
        float v = g_out[i] + bias[i & 127];
        dst[i] = fmaxf(v, 0.0f);
    }
}

// ---------------- MLP tail: relu(in@W2+b2) @ W3 + b3 (warp per row) ----------------
__global__ void k_mlp_tail(const float* __restrict__ in, const float* __restrict__ W2,
                           const float* __restrict__ b2, const float* __restrict__ W3,
                           const float* __restrict__ b3, float* __restrict__ out) {
    __shared__ float sW2[128 * 64];
    __shared__ float sW3[64];
    __shared__ float sb2[64];
    for (int i = threadIdx.x; i < 128 * 64; i += blockDim.x) sW2[i] = W2[i];
    if (threadIdx.x < 64) { sW3[threadIdx.x] = W3[threadIdx.x]; sb2[threadIdx.x] = b2[threadIdx.x]; }
    __syncthreads();
    int lane = threadIdx.x & 31;
    int w    = (blockIdx.x * blockDim.x + threadIdx.x) >> 5;
    int nw   = (gridDim.x * blockDim.x) >> 5;
    float bb3 = b3[0];
    for (int r = w; r < N_NODES; r += nw) {
        const float* row = in + (size_t)r * 128;
        float a[4];
        a[0] = row[lane]; a[1] = row[lane + 32]; a[2] = row[lane + 64]; a[3] = row[lane + 96];
        float acc0 = sb2[lane * 2], acc1 = sb2[lane * 2 + 1];
#pragma unroll
        for (int j = 0; j < 4; ++j) {
#pragma unroll
            for (int kk = 0; kk < 32; ++kk) {
                float ak = __shfl_sync(0xffffffffu, a[j], kk);
                int k = j * 32 + kk;
                acc0 += ak * sW2[k * 64 + lane * 2];
                acc1 += ak * sW2[k * 64 + lane * 2 + 1];
            }
        }
        acc0 = fmaxf(acc0, 0.f); acc1 = fmaxf(acc1, 0.f);
        float p = acc0 * sW3[lane * 2] + acc1 * sW3[lane * 2 + 1];
#pragma unroll
        for (int off = 16; off; off >>= 1) p += __shfl_down_sync(0xffffffffu, p, off);
        if (lane == 0) out[r] = p + bb3;
    }
}

// ---------------- host launch ----------------
extern "C" void kernel_launch(void* const* d_in, const int* in_sizes, int n_in,
                              void* d_out, int out_size) {
    const float* x  = (const float*)d_in[0];
    const void*  ei = d_in[1];               // int32 or int64 — detected on device
    const float* ea = (const float*)d_in[2];
    const float* c1_Wl  = (const float*)d_in[3];
    const float* c1_bl  = (const float*)d_in[4];
    const float* c1_Wr  = (const float*)d_in[5];
    const float* c1_br  = (const float*)d_in[6];
    const float* c1_We  = (const float*)d_in[7];
    const float* c1_att = (const float*)d_in[8];
    const float* c1_bias= (const float*)d_in[9];
    const float* c2_Wl  = (const float*)d_in[10];
    const float* c2_bl  = (const float*)d_in[11];
    const float* c2_Wr  = (const float*)d_in[12];
    const float* c2_br  = (const float*)d_in[13];
    const float* c2_We  = (const float*)d_in[14];
    const float* c2_att = (const float*)d_in[15];
    const float* c2_bias= (const float*)d_in[16];
    const float* W1 = (const float*)d_in[17];
    const float* b1 = (const float*)d_in[18];
    const float* W2 = (const float*)d_in[19];
    const float* b2 = (const float*)d_in[20];
    const float* W3 = (const float*)d_in[21];
    const float* b3 = (const float*)d_in[22];
    float* outp = (float*)d_out;

    float *p_xl, *p_xr, *p_h, *p_out, *p_mlp, *p_loop, *p_cnt, *p_amax, *p_den;
    cudaGetSymbolAddress((void**)&p_xl,   g_xl);
    cudaGetSymbolAddress((void**)&p_xr,   g_xr);
    cudaGetSymbolAddress((void**)&p_h,    g_h);
    cudaGetSymbolAddress((void**)&p_out,  g_out);
    cudaGetSymbolAddress((void**)&p_mlp,  g_mlp);
    cudaGetSymbolAddress((void**)&p_loop, g_loop);
    cudaGetSymbolAddress((void**)&p_cnt,  g_cnt);
    cudaGetSymbolAddress((void**)&p_amax, g_amax);
    cudaGetSymbolAddress((void**)&p_den,  g_den);

    cudaFuncSetAttribute(k_gemm128,    cudaFuncAttributeMaxDynamicSharedMemorySize, 128 * 128 * 4);
    cudaFuncSetAttribute(k_edge_logit, cudaFuncAttributeMaxDynamicSharedMemorySize, E_DIM * HC * 4);

    const int T = 256;
    const int gemmBlocks = 444;   // 148 SMs * 3
    const int edgeBlocks = 444;
    const int aggBlocks  = 1024;

    // ---- canonicalize edge index (dtype-robust) ----
    k_detect<<<1, 256>>>((const int*)ei);
    k_convert<<<(E_EDGES + T - 1) / T, T>>>(ei);

    // ---- pre-pass: in-degree + mean incoming edge_attr (loop_attr) ----
    k_fill<<<(N_NODES + T - 1) / T, T>>>(p_cnt, 0.0f, N_NODES);
    k_fill<<<(N_NODES * E_PAD + T - 1) / T, T>>>(p_loop, 0.0f, N_NODES * E_PAD);
    k_degree<<<1024, T>>>(ea);
    k_loopdiv<<<(N_NODES * E_PAD + T - 1) / T, T>>>();

    for (int layer = 0; layer < 2; ++layer) {
        const float* inFeat = (layer == 0) ? x : p_h;
        const float* Wl   = (layer == 0) ? c1_Wl   : c2_Wl;
        const float* bl   = (layer == 0) ? c1_bl   : c2_bl;
        const float* Wr   = (layer == 0) ? c1_Wr   : c2_Wr;
        const float* br   = (layer == 0) ? c1_br   : c2_br;
        const float* Wep  = (layer == 0) ? c1_We   : c2_We;
        const float* attp = (layer == 0) ? c1_att  : c2_att;
        const float* bp   = (layer == 0) ? c1_bias : c2_bias;

        k_gemm128<<<gemmBlocks, T, 128 * 128 * 4>>>(inFeat, Wl, bl, p_xl, N_NODES, 0);
        k_gemm128<<<gemmBlocks, T, 128 * 128 * 4>>>(inFeat, Wr, br, p_xr, N_NODES, 0);

        k_fill<<<(N_NODES * NHEAD + T - 1) / T, T>>>(p_amax, -3.0e38f, N_NODES * NHEAD);
        k_fill<<<(N_NODES * NHEAD + T - 1) / T, T>>>(p_den, 0.0f, N_NODES * NHEAD);
        k_fill<<<(N_NODES * HC + T - 1) / T, T>>>(p_out, 0.0f, N_NODES * HC);

        k_edge_logit<<<edgeBlocks, T, E_DIM * HC * 4>>>(ea, Wep, attp);
        k_edge_den<<<(E2 + T - 1) / T, T>>>();
        k_edge_agg<<<aggBlocks, T>>>();

        k_bias_relu<<<(N_NODES * HC + T - 1) / T, T>>>(bp, p_h, N_NODES * HC);
    }

    // ---- MLP head ----
    k_gemm128<<<gemmBlocks, T, 128 * 128 * 4>>>(p_h, W1, b1, p_mlp, N_NODES, 1);
    k_mlp_tail<<<gemmBlocks, T>>>(p_mlp, W2, b2, W3, b3, outp);
}